// round 16
// baseline (speedup 1.0000x reference)
#include <cuda_runtime.h>
#include <cuda_bf16.h>

#define D        512
#define NTAU     100
#define HSLOTS   128                 // rings: tag-gated, >=27-step overwrite margin
#define XCTAS    32
#define YCTAS    32
#define WARPS    16                  // compute warps per CTA (1 row each)
#define THREADS  ((WARPS + 1) * 32)  // 544: 16 compute + 1 poller warp

// Tagged words: {hi32: tag = step+1, lo32: float}. Relaxed-atomic b64 =>
// single-copy atomic (tearing-proof; proven R6..R15).
__device__ unsigned long long g_tag [HSLOTS * D];   // x history ring
__device__ unsigned long long g_yacc[HSLOTS * D];   // reduced W2·y_j per row

__device__ __forceinline__ unsigned long long make_tw(unsigned tag, float x) {
    return ((unsigned long long)tag << 32) | (unsigned long long)__float_as_uint(x);
}
__device__ __forceinline__ unsigned long long ld_g(const unsigned long long* p) {
    unsigned long long v;
    asm volatile("ld.relaxed.gpu.global.b64 %0, [%1];" : "=l"(v) : "l"(p) : "memory");
    return v;
}
__device__ __forceinline__ void st_g(unsigned long long* p, unsigned long long v) {
    asm volatile("st.relaxed.gpu.global.b64 [%0], %1;" :: "l"(p), "l"(v) : "memory");
}

// x-CTAs: poller arrives (never waits), compute syncs — proven R12/R15 pattern.
#define TILE_ARRIVE() asm volatile("bar.arrive 1, %0;" :: "n"(THREADS) : "memory")
#define TILE_WAIT()   asm volatile("bar.sync   1, %0;" :: "n"(THREADS) : "memory")
// y-CTAs: FULL barrier both sides (gather never backpressured locally).
#define YBAR()        asm volatile("bar.sync   2, %0;" :: "n"(THREADS) : "memory")

// fast tanh: 1 - 2/(exp(2z)+1); saturations exact (proven R12).
__device__ __forceinline__ float tanh_fast(float z) {
    const float e = __expf(2.0f * z);
    return 1.0f - __fdividef(2.0f, e + 1.0f);
}

__global__ void reset_kernel() {     // <<<512, 256>>> = 2 * HSLOTS * D words
    const int i = blockIdx.x * 256 + threadIdx.x;
    if (i < HSLOTS * D) g_tag[i] = 0ULL;
    else                g_yacc[i - HSLOTS * D] = 0ULL;
}

__global__ void __launch_bounds__(THREADS, 1) ndde_kernel(
    const float* __restrict__ x0,  const float* __restrict__ tau,
    const float* __restrict__ W1,  const float* __restrict__ W2,
    const float* __restrict__ b,   float* __restrict__ out, int N)
{
    __shared__ __align__(16) float sx[2][D];   // double-buffered tile

    const int  lane = threadIdx.x & 31;
    const int  warp = threadIdx.x >> 5;
    const long NP1  = (long)N + 1;

    if (blockIdx.x < XCTAS) {
        // ======================= X-CTAs =======================
        if (warp == WARPS) {
            // ---- PIPELINED poller: two rounds (A/B) always in flight ----
            // Discovery granularity ~ half an L2 round-trip instead of a full
            // serialized round (R15 lesson: retry quantization dominated).
            for (int j = 0; j < N; ++j) {
                const unsigned long long* xs =
                    &g_tag[(size_t)(j & (HSLOTS - 1)) * D];
                const unsigned need = (unsigned)(j + 1);
                float* tile = sx[j & 1];
                unsigned long long A[16], B[16];
                #pragma unroll
                for (int i = 0; i < 16; ++i) A[i] = ld_g(xs + lane + 32 * i);
                #pragma unroll
                for (int i = 0; i < 16; ++i) B[i] = ld_g(xs + lane + 32 * i);
                for (;;) {
                    bool ok = true;
                    #pragma unroll
                    for (int i = 0; i < 16; ++i)
                        ok &= ((unsigned)(A[i] >> 32) >= need);
                    if (ok) {
                        #pragma unroll
                        for (int i = 0; i < 16; ++i)
                            tile[lane + 32 * i] = __uint_as_float((unsigned)A[i]);
                        break;
                    }
                    #pragma unroll
                    for (int i = 0; i < 16; ++i)        // reissue A in flight
                        A[i] = ld_g(xs + lane + 32 * i);
                    ok = true;
                    #pragma unroll
                    for (int i = 0; i < 16; ++i)
                        ok &= ((unsigned)(B[i] >> 32) >= need);
                    if (ok) {
                        #pragma unroll
                        for (int i = 0; i < 16; ++i)
                            tile[lane + 32 * i] = __uint_as_float((unsigned)B[i]);
                        break;
                    }
                    #pragma unroll
                    for (int i = 0; i < 16; ++i)        // reissue B in flight
                        B[i] = ld_g(xs + lane + 32 * i);
                }
                TILE_ARRIVE();
            }
            return;
        }
        // ---- compute warp: one row ----
        const int row = blockIdx.x * WARPS + warp;
        float xcur = __ldg(x0 + row);
        if (lane == 0) {
            st_g(&g_tag[row], make_tw(1u, xcur));   // x_0, tag 1
            out[(long)row * NP1] = xcur;
        }
        float4 w1q[4];                               // k = 128g + 4*lane + c
        const float4* W1v = (const float4*)(W1 + (long)row * D);
        #pragma unroll
        for (int g = 0; g < 4; ++g) w1q[g] = __ldg(W1v + g * 32 + lane);
        const float dt  = 0.01f * __ldg(tau);
        const float b_r = __ldg(b + row);

        for (int j = 0; j < N; ++j) {
            // prefetch this row's reduced W2·y_j (latency hidden by TILE_WAIT)
            const unsigned long long* yap =
                &g_yacc[(size_t)(j & (HSLOTS - 1)) * D + row];
            unsigned long long ya = 0ULL;
            if (lane == 0) ya = ld_g(yap);

            TILE_WAIT();                             // tile j ready

            const float4* xv = (const float4*)sx[j & 1];
            float4 xq[4];
            #pragma unroll
            for (int g = 0; g < 4; ++g) xq[g] = xv[g * 32 + lane];
            float a0 = 0.f, a1 = 0.f;
            #pragma unroll
            for (int g = 0; g < 4; ++g) {
                a0 = fmaf(w1q[g].x, xq[g].x, a0);
                a1 = fmaf(w1q[g].y, xq[g].y, a1);
                a0 = fmaf(w1q[g].z, xq[g].z, a0);
                a1 = fmaf(w1q[g].w, xq[g].w, a1);
            }
            float acc = a0 + a1;
            #pragma unroll
            for (int off = 16; off; off >>= 1)
                acc += __shfl_xor_sync(0xffffffffu, acc, off);

            if (lane == 0) {
                while ((unsigned)(ya >> 32) < (unsigned)(j + 1))
                    ya = ld_g(yap);                  // ~never spins steady-state
                const float z = acc + __uint_as_float((unsigned)ya) + b_r;
                xcur = fmaf(dt, tanh_fast(z), xcur);
                st_g(&g_tag[(size_t)((j + 1) & (HSLOTS - 1)) * D + row],
                     make_tw((unsigned)(j + 2), xcur));
                out[(long)row * NP1 + (j + 1)] = xcur;
            }
        }
        return;
    }

    // ======================= Y-CTAs (trail 100 steps) =======================
    const int ysteady = (N > NTAU) ? (N - NTAU) : 0;   // # of gathered steps
    if (warp == WARPS) {
        // ---- y poller: gather x_{jn-NTAU} tiles (no spin in steady state) ----
        for (int t = 0; t < ysteady; ++t) {
            const int jn = NTAU + t;
            const unsigned long long* xs =
                &g_tag[(size_t)((jn - NTAU) & (HSLOTS - 1)) * D];
            const unsigned need = (unsigned)(jn - NTAU + 1);
            unsigned long long v[16];
            unsigned stale = 0xFFFFu;
            do {
                #pragma unroll
                for (int i = 0; i < 16; ++i)
                    if (stale & (1u << i))
                        v[i] = ld_g(xs + lane + 32 * i);
                #pragma unroll
                for (int i = 0; i < 16; ++i)
                    if ((stale & (1u << i)) && (unsigned)(v[i] >> 32) >= need)
                        stale &= ~(1u << i);
            } while (stale);
            #pragma unroll
            for (int i = 0; i < 16; ++i)
                sx[jn & 1][lane + 32 * i] = __uint_as_float((unsigned)v[i]);
            YBAR();                                  // full bar: paced by compute
        }
        return;
    }
    // ---- y compute warp: one row ----
    {
        const int row = (blockIdx.x - XCTAS) * WARPS + warp;
        float4 w2q[4];
        const float4* W2v = (const float4*)(W2 + (long)row * D);
        #pragma unroll
        for (int g = 0; g < 4; ++g) w2q[g] = __ldg(W2v + g * 32 + lane);

        // constant W2·x0 for jn < NTAU, published immediately (unblocks x j=0)
        const float4* X0v = (const float4*)x0;
        float a0 = 0.f, a1 = 0.f;
        #pragma unroll
        for (int g = 0; g < 4; ++g) {
            const float4 xq = __ldg(X0v + g * 32 + lane);
            a0 = fmaf(w2q[g].x, xq.x, a0);
            a1 = fmaf(w2q[g].y, xq.y, a1);
            a0 = fmaf(w2q[g].z, xq.z, a0);
            a1 = fmaf(w2q[g].w, xq.w, a1);
        }
        float sc = a0 + a1;
        #pragma unroll
        for (int off = 16; off; off >>= 1)
            sc += __shfl_xor_sync(0xffffffffu, sc, off);
        if (lane == 0) {
            const int lim = (N < NTAU) ? N : NTAU;
            for (int jn = 0; jn < lim; ++jn)
                st_g(&g_yacc[(size_t)(jn & (HSLOTS - 1)) * D + row],
                     make_tw((unsigned)(jn + 1), sc));
        }

        for (int t = 0; t < ysteady; ++t) {
            const int jn = NTAU + t;
            YBAR();                                  // tile jn ready
            const float4* yv = (const float4*)sx[jn & 1];
            float s0 = 0.f, s1 = 0.f;
            #pragma unroll
            for (int g = 0; g < 4; ++g) {
                const float4 yq = yv[g * 32 + lane];
                s0 = fmaf(w2q[g].x, yq.x, s0);
                s1 = fmaf(w2q[g].y, yq.y, s1);
                s0 = fmaf(w2q[g].z, yq.z, s0);
                s1 = fmaf(w2q[g].w, yq.w, s1);
            }
            float s = s0 + s1;
            #pragma unroll
            for (int off = 16; off; off >>= 1)
                s += __shfl_xor_sync(0xffffffffu, s, off);
            if (lane == 0)
                st_g(&g_yacc[(size_t)(jn & (HSLOTS - 1)) * D + row],
                     make_tw((unsigned)(jn + 1), s));
        }
    }
}

extern "C" void kernel_launch(void* const* d_in, const int* in_sizes, int n_in,
                              void* d_out, int out_size) {
    const float* x0  = (const float*)d_in[0];
    const float* tau = (const float*)d_in[1];
    const float* W1  = (const float*)d_in[2];
    const float* W2  = (const float*)d_in[3];
    const float* b   = (const float*)d_in[4];
    float* out = (float*)d_out;

    const int N = out_size / D - 1;    // out is [D, N+1]

    reset_kernel<<<512, 256>>>();      // zero rings (graph-replay determinism)
    ndde_kernel<<<XCTAS + YCTAS, THREADS>>>(x0, tau, W1, W2, b, out, N);
}